// round 12
// baseline (speedup 1.0000x reference)
#include <cuda_runtime.h>
#include <cstdint>

// 26 node coordinates (compile-time __constant__ init; no runtime copy)
__constant__ float2 c_nodes[26] = {
    {0.5454545454545454f, 0.76f}, {0.6022727272727273f, 0.76f},
    {0.5454545454545454f, 0.86f}, {0.6022727272727273f, 0.86f},
    {0.4772727272727273f, 0.76f}, {0.42045454545454547f, 0.76f},
    {0.42045454545454547f, 0.86f}, {0.4772727272727273f, 0.86f},
    {0.32954545454545453f, 0.808f}, {0.42045454545454547f, 0.48f},
    {0.4772727272727273f, 0.48f}, {0.4772727272727273f, 0.38f},
    {0.42045454545454547f, 0.38f}, {0.32954545454545453f, 0.428f},
    {0.5727272727272728f, 0.62f}, {0.7613636363636364f, 0.76f},
    {0.8181818181818182f, 0.76f}, {0.8181818181818182f, 0.86f},
    {0.7613636363636364f, 0.86f}, {0.7909090909090909f, 0.62f},
    {0.9431818181818182f, 0.76f}, {1.0f, 0.76f},
    {1.0f, 0.86f}, {0.9431818181818182f, 0.86f},
    {0.9727272727272728f, 0.62f}, {0.9727272727272728f, 1.0f}
};

// Row = 272 floats = 68 float4. Within-row float4 index w:
//   w=0: x[0..3]; w=1: {x4,x5,e1_0,e1_1}; w in [2,33): e1 (aligned in shifted buf);
//   w=33: {e1_126,e1_127,x6,x7}; w=34: {x8,x9,e2_0,e2_1}; w in [35,66): e2;
//   w=66: {e2_126,e2_127,x10,x11}; w=67: x[12..15].
// Main pass assumes idx=0 (emb row 0) for ALL rows; rare idx!=0 rows are
// patched afterwards (correct regardless of match frequency).

constexpr int ROWS_PER_BLOCK = 64;   // 16 warps x 4 rows
constexpr int THREADS = 512;

template<int K>
__device__ __forceinline__ void main_iter(
    int lane,
    const float* __restrict__ xg,     // smem x, 4 rows (64 floats)
    const float* __restrict__ rs,     // smem shifted emb row0 (132 floats)
    float2 rs2, float2 rs128,
    float4* __restrict__ ob)          // out base of 4-row span (float4)
{
    constexpr int gs = K * 32;
    constexpr int ra = gs / 68;
    constexpr int rb = (gs + 31 < 272 ? gs + 31 : 271) / 68;
    int h = gs + lane;
    int row, w;
    if constexpr (ra == rb) {
        row = ra;
        w = gs - 68 * ra + lane;
    } else {
        constexpr int split = 68 * rb - gs;
        bool hi = lane >= split;
        row = hi ? rb : ra;
        w = (hi ? gs - 68 * rb : gs - 68 * ra) + lane;
    }
    const float* xr = xg + row * 16;

    float4 v;
    bool pure = (w >= 2 && w < 33) || (w >= 35 && w < 66);
    if (pure) {
        int a = (w < 33) ? 4 * w - 4 : 4 * w - 136;   // aligned LDS.128
        v = *reinterpret_cast<const float4*>(rs + a);
    } else {
        if (w == 0)       v = *reinterpret_cast<const float4*>(xr);
        else if (w == 1)  v = make_float4(xr[4], xr[5], rs2.x, rs2.y);
        else if (w == 33) v = make_float4(rs128.x, rs128.y, xr[6], xr[7]);
        else if (w == 34) v = make_float4(xr[8], xr[9], rs2.x, rs2.y);
        else if (w == 66) v = make_float4(rs128.x, rs128.y, xr[10], xr[11]);
        else              v = *reinterpret_cast<const float4*>(xr + 12);
    }
    if (K < 8 || lane < 16)
        __stcs(&ob[h], v);
}

__global__ __launch_bounds__(THREADS) void pe_kernel(
    const float* __restrict__ x,
    const float* __restrict__ emb,
    float* __restrict__ out,
    int rows)
{
    __shared__ float4 sx4[ROWS_PER_BLOCK * 4];   // staged x (4KB)
    __shared__ float4 rs4[33];                   // shifted emb row0 (132 floats)

    int block_row0 = blockIdx.x * ROWS_PER_BLOCK;
    int t = threadIdx.x;

    // Stage x (coalesced float2 per thread) and shifted emb row 0
    reinterpret_cast<float2*>(sx4)[t] =
        reinterpret_cast<const float2*>(x)[(size_t)block_row0 * 8 + t];
    float* rs = reinterpret_cast<float*>(rs4);
    if (t < 128) rs[t + 2] = emb[t];             // emb[j] -> rs[j+2]
    if (t == 128) { rs[0] = 0.f; rs[1] = 0.f; rs[130] = 0.f; rs[131] = 0.f; }
    __syncthreads();

    const float* sxf = reinterpret_cast<const float*>(sx4);
    const float2* sx2 = reinterpret_cast<const float2*>(sx4);

    int warp = t >> 5;
    int lane = t & 31;
    int r0 = warp * 4;

    bool active = lane < 26;
    float nx = 0.f, ny = 0.f, tx = -1.f, ty = -1.f;
    if (active) {
        float2 n = c_nodes[lane];
        nx = n.x; ny = n.y;
        tx = 0.01f + 1e-5f * fabsf(nx);
        ty = 0.01f + 1e-5f * fabsf(ny);
    }

    // Ballots for the 4 rows (uniform across warp); kept only for patching
    int idx1[4], idx2[4];
    #pragma unroll
    for (int rr = 0; rr < 4; rr++) {
        float2 pt1 = sx2[(r0 + rr) * 8 + 2];     // floats 4,5
        float2 pt2 = sx2[(r0 + rr) * 8 + 4];     // floats 8,9
        bool m1 = active && (fabsf(pt1.x - nx) <= tx) && (fabsf(pt1.y - ny) <= ty);
        bool m2 = active && (fabsf(pt2.x - nx) <= tx) && (fabsf(pt2.y - ny) <= ty);
        idx1[rr] = __ffs(__ballot_sync(0xffffffffu, m1));  // 1-based == argmax+1
        idx2[rr] = __ffs(__ballot_sync(0xffffffffu, m2));
    }

    // ── Main pass: 8.5 aligned STG.128 iterations, smem-only sources,
    //    independent of ballots (assumes emb row 0 everywhere)
    float2 rs2   = *reinterpret_cast<const float2*>(rs + 2);
    float2 rs128 = *reinterpret_cast<const float2*>(rs + 128);
    const float* xg = sxf + r0 * 16;
    float4* ob = reinterpret_cast<float4*>(out) + (size_t)(block_row0 + r0) * 68;

    main_iter<0>(lane, xg, rs, rs2, rs128, ob);
    main_iter<1>(lane, xg, rs, rs2, rs128, ob);
    main_iter<2>(lane, xg, rs, rs2, rs128, ob);
    main_iter<3>(lane, xg, rs, rs2, rs128, ob);
    main_iter<4>(lane, xg, rs, rs2, rs128, ob);
    main_iter<5>(lane, xg, rs, rs2, rs128, ob);
    main_iter<6>(lane, xg, rs, rs2, rs128, ob);
    main_iter<7>(lane, xg, rs, rs2, rs128, ob);
    main_iter<8>(lane, xg, rs, rs2, rs128, ob);

    // Order main-pass stores before patch stores (cross-lane same-address)
    __syncthreads();

    // ── Patch pass: rewrite emb segments of rows whose idx != 0 (rare, uniform)
    const float2* emb2 = reinterpret_cast<const float2*>(emb);
    #pragma unroll
    for (int rr = 0; rr < 4; rr++) {
        if (idx1[rr] != 0) {
            const float2* e1 = emb2 + (size_t)idx1[rr] * 64;
            float2* o = reinterpret_cast<float2*>(out)
                      + (size_t)(block_row0 + r0 + rr) * 136;
            __stcs(&o[3 + lane],  e1[lane]);
            __stcs(&o[35 + lane], e1[32 + lane]);
        }
        if (idx2[rr] != 0) {
            const float2* e2 = emb2 + (size_t)idx2[rr] * 64;
            float2* o = reinterpret_cast<float2*>(out)
                      + (size_t)(block_row0 + r0 + rr) * 136;
            __stcs(&o[69 + lane],  e2[lane]);
            __stcs(&o[101 + lane], e2[32 + lane]);
        }
    }
}

extern "C" void kernel_launch(void* const* d_in, const int* in_sizes, int n_in,
                              void* d_out, int out_size)
{
    const float* x;
    const float* emb;
    int xsz;
    if (in_sizes[0] > in_sizes[1]) {
        x = (const float*)d_in[0]; emb = (const float*)d_in[1]; xsz = in_sizes[0];
    } else {
        x = (const float*)d_in[1]; emb = (const float*)d_in[0]; xsz = in_sizes[1];
    }
    int rows = xsz / 16;                                       // 262144
    int blocks = (rows + ROWS_PER_BLOCK - 1) / ROWS_PER_BLOCK; // 4096 (exact)
    pe_kernel<<<blocks, THREADS>>>(x, emb, (float*)d_out, rows);
}

// round 13
// speedup vs baseline: 1.2536x; 1.2536x over previous
#include <cuda_runtime.h>
#include <cstdint>

// 26 node coordinates (compile-time __constant__ init; no runtime copy)
__constant__ float2 c_nodes[26] = {
    {0.5454545454545454f, 0.76f}, {0.6022727272727273f, 0.76f},
    {0.5454545454545454f, 0.86f}, {0.6022727272727273f, 0.86f},
    {0.4772727272727273f, 0.76f}, {0.42045454545454547f, 0.76f},
    {0.42045454545454547f, 0.86f}, {0.4772727272727273f, 0.86f},
    {0.32954545454545453f, 0.808f}, {0.42045454545454547f, 0.48f},
    {0.4772727272727273f, 0.48f}, {0.4772727272727273f, 0.38f},
    {0.42045454545454547f, 0.38f}, {0.32954545454545453f, 0.428f},
    {0.5727272727272728f, 0.62f}, {0.7613636363636364f, 0.76f},
    {0.8181818181818182f, 0.76f}, {0.8181818181818182f, 0.86f},
    {0.7613636363636364f, 0.86f}, {0.7909090909090909f, 0.62f},
    {0.9431818181818182f, 0.76f}, {1.0f, 0.76f},
    {1.0f, 0.86f}, {0.9431818181818182f, 0.86f},
    {0.9727272727272728f, 0.62f}, {0.9727272727272728f, 1.0f}
};

// Output row = 136 float2:
//   c in [0,3)->x2[c]; [3,67)->e1[c-3]; [67,69)->x2[c-64];
//   [69,133)->e2[c-69]; [133,136)->x2[c-128]
// 4 rows = 544 float2 = 17 x 256B, iterated flat: every store iteration is a
// dense 256B-aligned burst; iteration geometry is constexpr (template<K>).
// Staging is WARP-LOCAL: each warp's 4 rows of x are exactly 32 float2 = one
// dense 256B LDG per warp -> stage into the warp's private smem slice and use
// __syncwarp only. No block-wide barrier anywhere; warps fully decoupled.

constexpr int ROWS_PER_BLOCK = 64;   // 16 warps x 4 rows; smem 4KB
constexpr int THREADS = 512;

template<int K>
__device__ __forceinline__ void do_iter(
    int lane,
    const float2* __restrict__ e1a, const float2* __restrict__ e1b,
    const float2* __restrict__ e2a, const float2* __restrict__ e2b,
    const float2* __restrict__ xa,  const float2* __restrict__ xb,
    float2* __restrict__ olane)
{
    constexpr int gs = K * 32;
    constexpr int ra = gs / 136;
    constexpr int rb = (gs + 31) / 136;
    constexpr int ca = gs - 136 * ra;        // c of lane 0 on low side
    float2 v;
    if constexpr (ra == rb) {
        if constexpr (ca >= 3 && ca + 31 < 67) {
            v = e1a[ca - 3 + lane];                    // pure e1: LDG only
        } else if constexpr (ca >= 69 && ca + 31 < 133) {
            v = e2a[ca - 69 + lane];                   // pure e2: LDG only
        } else {
            int c = ca + lane;
            if (c < 3)        v = xa[c];
            else if (c < 67)  v = e1a[c - 3];
            else if (c < 69)  v = xa[c - 64];
            else if (c < 133) v = e2a[c - 69];
            else              v = xa[c - 128];
        }
    } else {
        constexpr int split = 136 * rb - gs;           // 8, 16 or 24
        constexpr int cb = gs - 136 * rb;              // negative
        bool hi = lane >= split;
        int c = (hi ? cb : ca) + lane;
        const float2* e1 = hi ? e1b : e1a;
        const float2* e2 = hi ? e2b : e2a;
        const float2* xr = hi ? xb : xa;
        if (c < 3)        v = xr[c];
        else if (c < 67)  v = e1[c - 3];
        else if (c < 69)  v = xr[c - 64];
        else if (c < 133) v = e2[c - 69];
        else              v = xr[c - 128];
    }
    __stcs(&olane[gs], v);
}

__global__ __launch_bounds__(THREADS) void pe_kernel(
    const float* __restrict__ x,
    const float* __restrict__ emb,
    float* __restrict__ out,
    int rows)
{
    __shared__ float2 sx2[THREADS];              // 4KB; 32 float2 per warp slice

    int block_row0 = blockIdx.x * ROWS_PER_BLOCK;
    int t = threadIdx.x;
    int warp = t >> 5;
    int lane = t & 31;

    // Warp-local stage: each warp loads ITS OWN 4 rows (dense 256B LDG.64)
    sx2[t] = reinterpret_cast<const float2*>(x)[(size_t)block_row0 * 8 + t];
    __syncwarp();

    const float2* wx = sx2 + warp * 32;          // this warp's 4 rows (32 float2)

    bool active = lane < 26;
    float nx = 0.f, ny = 0.f, tx = -1.f, ty = -1.f;
    if (active) {
        float2 n = c_nodes[lane];
        nx = n.x; ny = n.y;
        tx = 0.01f + 1e-5f * fabsf(nx);
        ty = 0.01f + 1e-5f * fabsf(ny);
    }

    const float2* emb2 = reinterpret_cast<const float2*>(emb);

    // Ballots for 4 rows -> per-row emb pointers (uniform across warp)
    const float2* e1p[4];
    const float2* e2p[4];
    const float2* xp[4];
    #pragma unroll
    for (int rr = 0; rr < 4; rr++) {
        float2 pt1 = wx[rr * 8 + 2];             // floats 4,5 of row rr
        float2 pt2 = wx[rr * 8 + 4];             // floats 8,9
        bool m1 = active && (fabsf(pt1.x - nx) <= tx) && (fabsf(pt1.y - ny) <= ty);
        bool m2 = active && (fabsf(pt2.x - nx) <= tx) && (fabsf(pt2.y - ny) <= ty);
        int idx1 = __ffs(__ballot_sync(0xffffffffu, m1));  // 1-based == argmax+1
        int idx2 = __ffs(__ballot_sync(0xffffffffu, m2));
        e1p[rr] = emb2 + (size_t)idx1 * 64;
        e2p[rr] = emb2 + (size_t)idx2 * 64;
        xp[rr]  = wx + rr * 8;
    }

    float2* olane = reinterpret_cast<float2*>(out)
                  + (size_t)(block_row0 + warp * 4) * 136 + lane;

#define ITER(K) do_iter<K>(lane, \
        e1p[(K*32)/136], e1p[((K*32)+31)/136], \
        e2p[(K*32)/136], e2p[((K*32)+31)/136], \
        xp[(K*32)/136],  xp[((K*32)+31)/136],  olane)
    ITER(0);  ITER(1);  ITER(2);  ITER(3);  ITER(4);  ITER(5);
    ITER(6);  ITER(7);  ITER(8);  ITER(9);  ITER(10); ITER(11);
    ITER(12); ITER(13); ITER(14); ITER(15); ITER(16);
#undef ITER
}

extern "C" void kernel_launch(void* const* d_in, const int* in_sizes, int n_in,
                              void* d_out, int out_size)
{
    const float* x;
    const float* emb;
    int xsz;
    if (in_sizes[0] > in_sizes[1]) {
        x = (const float*)d_in[0]; emb = (const float*)d_in[1]; xsz = in_sizes[0];
    } else {
        x = (const float*)d_in[1]; emb = (const float*)d_in[0]; xsz = in_sizes[1];
    }
    int rows = xsz / 16;                                       // 262144
    int blocks = (rows + ROWS_PER_BLOCK - 1) / ROWS_PER_BLOCK; // 4096 (exact)
    pe_kernel<<<blocks, THREADS>>>(x, emb, (float*)d_out, rows);
}